// round 14
// baseline (speedup 1.0000x reference)
#include <cuda_runtime.h>
#include <cstdint>

#define TPB 256

struct f8 { float4 a, b; };

__device__ __forceinline__ f8 ldcs8(const float* p) {
    f8 r;
    asm volatile("ld.global.cs.v8.f32 {%0,%1,%2,%3,%4,%5,%6,%7}, [%8];"
        : "=f"(r.a.x), "=f"(r.a.y), "=f"(r.a.z), "=f"(r.a.w),
          "=f"(r.b.x), "=f"(r.b.y), "=f"(r.b.z), "=f"(r.b.w)
        : "l"(p));
    return r;
}
__device__ __forceinline__ void stcs4(float4* p, float4 v) { __stcs(p, v); }

__global__ __launch_bounds__(TPB, 6) void tp_kernel(
    const float* __restrict__ x0, const float* __restrict__ y0,
    const float* __restrict__ x1, const float* __restrict__ y1,
    const float* __restrict__ x2, const float* __restrict__ y2,
    float* __restrict__ out, long long NC)
{
    __shared__ float sA[TPB * 9];
    __shared__ float sB[TPB * 9];
    __shared__ float su[TPB * 3];
    __shared__ float sv[TPB * 3];
    __shared__ float sa[TPB];
    __shared__ float sb[TPB];

    const long long base = (long long)blockIdx.x * TPB;
    const int t = threadIdx.x;
    long long rem = NC - base;
    const int npair = rem < TPB ? (int)rem : TPB;
    const bool full = (npair == TPB);

    if (full) {
        // ---- 256-bit front-batched staging.
        //      Streams in 32B (v8) words: A,B: 288 each; u,v: 96; a,b: 32.
        //        every thread : A8[t], B8[t]
        //        t in [  0, 32): A8[256+t],       a8[t]
        //        t in [ 32, 64): B8[256+(t-32)],  b8[t-32]
        //        t in [ 64,160): u8[t-64]
        //        t in [160,256): v8[t-160]
        //      Max live payload: 4 x v8 = 32 regs. Masks warp-uniform.
        const float* gA = x2 + base * 9;
        const float* gB = y2 + base * 9;
        const float* gu = x1 + base * 3;
        const float* gv = y1 + base * 3;
        const float* ga = x0 + base;
        const float* gb = y0 + base;

        const bool e0 = (t < 32);
        const bool e1 = (t >= 32 && t < 64);
        const bool muv = (t >= 64);
        const bool mu  = (t >= 64 && t < 160);

        f8 rA0 = ldcs8(gA + 8 * t);
        f8 rB0 = ldcs8(gB + 8 * t);
        f8 rx, ry, ruv;
        if (e0) { rx = ldcs8(gA + 8 * (256 + t));        ry = ldcs8(ga + 8 * t); }
        if (e1) { rx = ldcs8(gB + 8 * (256 + (t - 32))); ry = ldcs8(gb + 8 * (t - 32)); }
        if (muv) ruv = mu ? ldcs8(gu + 8 * (t - 64)) : ldcs8(gv + 8 * (t - 160));

        float4* s4A = (float4*)sA;
        float4* s4B = (float4*)sB;
        float4* s4u = (float4*)su;
        float4* s4v = (float4*)sv;
        float4* s4a = (float4*)sa;
        float4* s4b = (float4*)sb;
        s4A[2 * t]     = rA0.a;
        s4A[2 * t + 1] = rA0.b;
        s4B[2 * t]     = rB0.a;
        s4B[2 * t + 1] = rB0.b;
        if (e0) {
            s4A[512 + 2 * t]     = rx.a;
            s4A[512 + 2 * t + 1] = rx.b;
            s4a[2 * t]     = ry.a;
            s4a[2 * t + 1] = ry.b;
        }
        if (e1) {
            int i = t - 32;
            s4B[512 + 2 * i]     = rx.a;
            s4B[512 + 2 * i + 1] = rx.b;
            s4b[2 * i]     = ry.a;
            s4b[2 * i + 1] = ry.b;
        }
        if (mu) {
            int i = t - 64;
            s4u[2 * i]     = ruv.a;
            s4u[2 * i + 1] = ruv.b;
        } else if (muv) {
            int i = t - 160;
            s4v[2 * i]     = ruv.a;
            s4v[2 * i + 1] = ruv.b;
        }
    } else {
        for (int i = t; i < npair * 9; i += TPB) { sA[i] = x2[base * 9 + i]; sB[i] = y2[base * 9 + i]; }
        for (int i = t; i < npair * 3; i += TPB) { su[i] = x1[base * 3 + i]; sv[i] = y1[base * 3 + i]; }
        for (int i = t; i < npair;     i += TPB) { sa[i] = x0[base + i];     sb[i] = y0[base + i]; }
    }
    __syncthreads();

    // ---- Per-pair compute. Results written straight back into this thread's
    //      OWN smem slots (slot t touched only by thread t between barriers). ----
    if (t < npair) {
        const float a = sa[t], b = sb[t];
        float u[3], v[3], A[9], B[9];
        #pragma unroll
        for (int i = 0; i < 3; i++) { u[i] = su[t * 3 + i]; v[i] = sv[t * 3 + i]; }
        #pragma unroll
        for (int i = 0; i < 9; i++) { A[i] = sA[t * 9 + i]; B[i] = sB[t * 9 + i]; }

        // z2 = a*B + b*A + u (x) v + A@B  -> sA[t*9+..]
        #pragma unroll
        for (int i = 0; i < 3; i++) {
            #pragma unroll
            for (int j = 0; j < 3; j++) {
                float s = fmaf(a, B[i * 3 + j], b * A[i * 3 + j]);
                s = fmaf(u[i], v[j], s);
                #pragma unroll
                for (int k = 0; k < 3; k++)
                    s = fmaf(A[i * 3 + k], B[k * 3 + j], s);
                sA[t * 9 + i * 3 + j] = s;
            }
        }
        // z1 = a*v + b*u + u.B + A.v  -> su[t*3+..]
        #pragma unroll
        for (int i = 0; i < 3; i++) {
            float s = fmaf(a, v[i], b * u[i]);
            #pragma unroll
            for (int d = 0; d < 3; d++) {
                s = fmaf(u[d], B[d * 3 + i], s);
                s = fmaf(A[i * 3 + d], v[d], s);
            }
            su[t * 3 + i] = s;
        }
        // z0 = a*b + u.v + <A,B>  -> sa[t]
        float z0 = a * b;
        #pragma unroll
        for (int i = 0; i < 3; i++) z0 = fmaf(u[i], v[i], z0);
        #pragma unroll
        for (int i = 0; i < 9; i++) z0 = fmaf(A[i], B[i], z0);
        sa[t] = z0;
    }
    __syncthreads();

    // ---- Coalesced streaming stores (proven v4 .cs path, load-balanced) ----
    float* o0 = out;
    float* o1 = out + NC;
    float* o2 = out + 4 * NC;
    if (full) {
        float4* g0 = (float4*)(o0 + base);
        float4* g1 = (float4*)(o1 + base * 3);
        float4* g2 = (float4*)(o2 + base * 9);
        const float4* s40 = (const float4*)sa;
        const float4* s41 = (const float4*)su;
        const float4* s42 = (const float4*)sA;
        stcs4(g2 + t,       s42[t]);
        stcs4(g2 + t + 256, s42[t + 256]);
        if (t < 192) stcs4(g1 + t, s41[t]);
        if (t >= 64 && t < 128) stcs4(g2 + (t - 64) + 512, s42[(t - 64) + 512]);
        if (t >= 128 && t < 192) stcs4(g0 + (t - 128), s40[t - 128]);
    } else {
        for (int i = t; i < npair;     i += TPB) o0[base + i]     = sa[i];
        for (int i = t; i < npair * 3; i += TPB) o1[base * 3 + i] = su[i];
        for (int i = t; i < npair * 9; i += TPB) o2[base * 9 + i] = sA[i];
    }
}

// ---- fallback: one thread per pair, any alignment ----
__global__ void tp_simple(
    const float* __restrict__ x0, const float* __restrict__ y0,
    const float* __restrict__ x1, const float* __restrict__ y1,
    const float* __restrict__ x2, const float* __restrict__ y2,
    float* __restrict__ out, long long NC)
{
    long long p = (long long)blockIdx.x * blockDim.x + threadIdx.x;
    if (p >= NC) return;
    float a = x0[p], b = y0[p];
    float u[3], v[3], A[9], B[9];
    #pragma unroll
    for (int i = 0; i < 3; i++) { u[i] = x1[p * 3 + i]; v[i] = y1[p * 3 + i]; }
    #pragma unroll
    for (int i = 0; i < 9; i++) { A[i] = x2[p * 9 + i]; B[i] = y2[p * 9 + i]; }

    float z0 = a * b;
    #pragma unroll
    for (int i = 0; i < 3; i++) z0 = fmaf(u[i], v[i], z0);
    #pragma unroll
    for (int i = 0; i < 9; i++) z0 = fmaf(A[i], B[i], z0);
    out[p] = z0;
    #pragma unroll
    for (int i = 0; i < 3; i++) {
        float s = fmaf(a, v[i], b * u[i]);
        #pragma unroll
        for (int d = 0; d < 3; d++) {
            s = fmaf(u[d], B[d * 3 + i], s);
            s = fmaf(A[i * 3 + d], v[d], s);
        }
        out[NC + p * 3 + i] = s;
    }
    #pragma unroll
    for (int i = 0; i < 3; i++)
        #pragma unroll
        for (int j = 0; j < 3; j++) {
            float s = fmaf(a, B[i * 3 + j], b * A[i * 3 + j]);
            s = fmaf(u[i], v[j], s);
            #pragma unroll
            for (int k = 0; k < 3; k++)
                s = fmaf(A[i * 3 + k], B[k * 3 + j], s);
            out[4 * NC + p * 9 + i * 3 + j] = s;
        }
}

extern "C" void kernel_launch(void* const* d_in, const int* in_sizes, int n_in,
                              void* d_out, int out_size)
{
    // out = (z0, z1, z2) concatenated: 13*NC floats
    const long long NC = (long long)out_size / 13;

    // Classify inputs by element count; x precedes y within each size class
    // in both plausible metadata orderings.
    const float *x0 = nullptr, *y0 = nullptr, *x1 = nullptr, *y1 = nullptr,
                *x2 = nullptr, *y2 = nullptr;
    for (int i = 0; i < n_in; i++) {
        long long s = in_sizes[i];
        const float* p = (const float*)d_in[i];
        if (s == NC)          { if (!x0) x0 = p; else y0 = p; }
        else if (s == 3 * NC) { if (!x1) x1 = p; else y1 = p; }
        else if (s == 9 * NC) { if (!x2) x2 = p; else y2 = p; }
    }

    // v8 path needs 32B-aligned stream bases (block offsets are multiples of
    // 1024/3072/9216 bytes, so base alignment is the only requirement).
    auto a32 = [](const void* p) { return (((uintptr_t)p) & 31) == 0; };
    bool ok = a32(x0) && a32(y0) && a32(x1) && a32(y1) &&
              a32(x2) && a32(y2) && a32(d_out) && (NC % 4 == 0);

    if (ok) {
        const int nblocks = (int)((NC + TPB - 1) / TPB);
        tp_kernel<<<nblocks, TPB>>>(x0, y0, x1, y1, x2, y2, (float*)d_out, NC);
    } else {
        const int nblocks = (int)((NC + 255) / 256);
        tp_simple<<<nblocks, 256>>>(x0, y0, x1, y1, x2, y2, (float*)d_out, NC);
    }
}

// round 15
// speedup vs baseline: 1.2417x; 1.2417x over previous
#include <cuda_runtime.h>
#include <cstdint>

#define TPB 256

__device__ __forceinline__ float4 ldcs4(const float4* p) { return __ldcs(p); }
__device__ __forceinline__ void stcs4(float4* p, float4 v) { __stcs(p, v); }

__global__ __launch_bounds__(TPB, 6) void tp_kernel(
    const float* __restrict__ x0, const float* __restrict__ y0,
    const float* __restrict__ x1, const float* __restrict__ y1,
    const float* __restrict__ x2, const float* __restrict__ y2,
    float* __restrict__ out, long long NC)
{
    __shared__ float sA[TPB * 9];
    __shared__ float sB[TPB * 9];
    __shared__ float su[TPB * 3];
    __shared__ float sv[TPB * 3];
    __shared__ float sa[TPB];
    __shared__ float sb[TPB];

    const long long base = (long long)blockIdx.x * TPB;
    const int t = threadIdx.x;
    long long rem = NC - base;
    const int npair = rem < TPB ? (int)rem : TPB;
    const bool full = (npair == TPB);

    if (full) {
        // ---- Load-balanced front-batched staging (v4 = the proven sweet spot;
        //      v8 regressed via L1tex wavefront splitting, R14).
        //      1664 float4 per block, 6-7 per thread, masks warp-uniform:
        //        every thread : A[t], A[t+256], B[t], B[t+256]
        //        t <  192     : u[t]
        //        t >=  64     : v[t-64]
        //        quadrant     : one of A3 / B3 / a / b
        const float4* gA = (const float4*)(x2 + base * 9);   // 576 float4
        const float4* gB = (const float4*)(y2 + base * 9);   // 576 float4
        const float4* gu = (const float4*)(x1 + base * 3);   // 192 float4
        const float4* gv = (const float4*)(y1 + base * 3);   // 192 float4
        const float4* ga = (const float4*)(x0 + base);       //  64 float4
        const float4* gb = (const float4*)(y0 + base);       //  64 float4

        const bool mu = (t < 192);
        const bool mv = (t >= 64);
        const int  q  = t >> 6;          // quadrant 0..3 (warp-uniform)

        float4 rA0 = ldcs4(gA + t);
        float4 rB0 = ldcs4(gB + t);
        float4 rA1 = ldcs4(gA + t + 256);
        float4 rB1 = ldcs4(gB + t + 256);
        float4 ru, rv, rex;
        if (mu) ru = ldcs4(gu + t);
        if (mv) rv = ldcs4(gv + (t - 64));
        if      (q == 0) rex = ldcs4(gA + t + 512);          // A3[0..63]
        else if (q == 1) rex = ldcs4(gB + (t - 64) + 512);   // B3[0..63]
        else if (q == 2) rex = ldcs4(ga + (t - 128));        // a[0..63]
        else             rex = ldcs4(gb + (t - 192));        // b[0..63]

        float4* s4A = (float4*)sA;
        float4* s4B = (float4*)sB;
        float4* s4u = (float4*)su;
        float4* s4v = (float4*)sv;
        float4* s4a = (float4*)sa;
        float4* s4b = (float4*)sb;
        s4A[t]       = rA0;
        s4B[t]       = rB0;
        s4A[t + 256] = rA1;
        s4B[t + 256] = rB1;
        if (mu) s4u[t] = ru;
        if (mv) s4v[t - 64] = rv;
        if      (q == 0) s4A[t + 512]        = rex;
        else if (q == 1) s4B[(t - 64) + 512] = rex;
        else if (q == 2) s4a[t - 128]        = rex;
        else             s4b[t - 192]        = rex;
    } else {
        for (int i = t; i < npair * 9; i += TPB) { sA[i] = x2[base * 9 + i]; sB[i] = y2[base * 9 + i]; }
        for (int i = t; i < npair * 3; i += TPB) { su[i] = x1[base * 3 + i]; sv[i] = y1[base * 3 + i]; }
        for (int i = t; i < npair;     i += TPB) { sa[i] = x0[base + i];     sb[i] = y0[base + i]; }
    }
    __syncthreads();

    // ---- Per-pair compute. Operands pulled fully into registers, results
    //      written straight back into this thread's OWN smem slots (slot t is
    //      touched only by thread t between the two barriers). ----
    if (t < npair) {
        const float a = sa[t], b = sb[t];
        float u[3], v[3], A[9], B[9];
        #pragma unroll
        for (int i = 0; i < 3; i++) { u[i] = su[t * 3 + i]; v[i] = sv[t * 3 + i]; }
        #pragma unroll
        for (int i = 0; i < 9; i++) { A[i] = sA[t * 9 + i]; B[i] = sB[t * 9 + i]; }

        // z2 = a*B + b*A + u (x) v + A@B  -> sA[t*9+..]
        #pragma unroll
        for (int i = 0; i < 3; i++) {
            #pragma unroll
            for (int j = 0; j < 3; j++) {
                float s = fmaf(a, B[i * 3 + j], b * A[i * 3 + j]);
                s = fmaf(u[i], v[j], s);
                #pragma unroll
                for (int k = 0; k < 3; k++)
                    s = fmaf(A[i * 3 + k], B[k * 3 + j], s);
                sA[t * 9 + i * 3 + j] = s;
            }
        }
        // z1 = a*v + b*u + u.B + A.v  -> su[t*3+..]
        #pragma unroll
        for (int i = 0; i < 3; i++) {
            float s = fmaf(a, v[i], b * u[i]);
            #pragma unroll
            for (int d = 0; d < 3; d++) {
                s = fmaf(u[d], B[d * 3 + i], s);
                s = fmaf(A[i * 3 + d], v[d], s);
            }
            su[t * 3 + i] = s;
        }
        // z0 = a*b + u.v + <A,B>  -> sa[t]
        float z0 = a * b;
        #pragma unroll
        for (int i = 0; i < 3; i++) z0 = fmaf(u[i], v[i], z0);
        #pragma unroll
        for (int i = 0; i < 9; i++) z0 = fmaf(A[i], B[i], z0);
        sa[t] = z0;
    }
    __syncthreads();

    // ---- Coalesced streaming stores, balanced 3/4/3/3 per quadrant:
    //        every thread : g2[t], g2[t+256]
    //        t <  192     : g1[t]
    //        t in [ 64,128): g2[512 + t-64]
    //        t >= 192     : g2[512 + 64 + (t-192) (wraps? no)] -- see below
    //      Quadrant counts: q0:3  q1:4  q2:3  q3:3  (was 3/4/4/2). ----
    float* o0 = out;
    float* o1 = out + NC;
    float* o2 = out + 4 * NC;
    if (full) {
        float4* g0 = (float4*)(o0 + base);
        float4* g1 = (float4*)(o1 + base * 3);
        float4* g2 = (float4*)(o2 + base * 9);
        const float4* s40 = (const float4*)sa;
        const float4* s41 = (const float4*)su;
        const float4* s42 = (const float4*)sA;
        stcs4(g2 + t,       s42[t]);
        stcs4(g2 + t + 256, s42[t + 256]);
        if (t < 192) stcs4(g1 + t, s41[t]);
        if (t >= 64 && t < 128) stcs4(g2 + (t - 64) + 512, s42[(t - 64) + 512]);
        if (t >= 192) stcs4(g0 + (t - 192), s40[t - 192]);
    } else {
        for (int i = t; i < npair;     i += TPB) o0[base + i]     = sa[i];
        for (int i = t; i < npair * 3; i += TPB) o1[base * 3 + i] = su[i];
        for (int i = t; i < npair * 9; i += TPB) o2[base * 9 + i] = sA[i];
    }
}

extern "C" void kernel_launch(void* const* d_in, const int* in_sizes, int n_in,
                              void* d_out, int out_size)
{
    // out = (z0, z1, z2) concatenated: 13*NC floats
    const long long NC = (long long)out_size / 13;

    // Classify inputs by element count; x precedes y within each size class
    // in both plausible metadata orderings.
    const float *x0 = nullptr, *y0 = nullptr, *x1 = nullptr, *y1 = nullptr,
                *x2 = nullptr, *y2 = nullptr;
    for (int i = 0; i < n_in; i++) {
        long long s = in_sizes[i];
        const float* p = (const float*)d_in[i];
        if (s == NC)          { if (!x0) x0 = p; else y0 = p; }
        else if (s == 3 * NC) { if (!x1) x1 = p; else y1 = p; }
        else if (s == 9 * NC) { if (!x2) x2 = p; else y2 = p; }
    }

    const int nblocks = (int)((NC + TPB - 1) / TPB);
    tp_kernel<<<nblocks, TPB>>>(x0, y0, x1, y1, x2, y2, (float*)d_out, NC);
}

// round 17
// speedup vs baseline: 1.2419x; 1.0002x over previous
#include <cuda_runtime.h>
#include <cstdint>

#define TPB 256

__device__ __forceinline__ float4 ldcs4(const float4* p) { return __ldcs(p); }
__device__ __forceinline__ void stcs4(float4* p, float4 v) { __stcs(p, v); }

__global__ __launch_bounds__(TPB, 6) void tp_kernel(
    const float* __restrict__ x0, const float* __restrict__ y0,
    const float* __restrict__ x1, const float* __restrict__ y1,
    const float* __restrict__ x2, const float* __restrict__ y2,
    float* __restrict__ out, long long NC)
{
    __shared__ float sA[TPB * 9];
    __shared__ float sB[TPB * 9];
    __shared__ float su[TPB * 3];
    __shared__ float sv[TPB * 3];

    const long long base = (long long)blockIdx.x * TPB;
    const int t = threadIdx.x;
    long long rem = NC - base;
    const int npair = rem < TPB ? (int)rem : TPB;
    const bool full = (npair == TPB);

    float a = 0.f, b = 0.f;

    if (full) {
        // ---- Front-batched staging, perfectly balanced: 6 vector loads per
        //      thread + 2 coalesced scalar loads (a,b bypass smem entirely —
        //      thread t owns element base+t). Masks warp-uniform (64-bounds):
        //        every thread : A[t], A[t+256], B[t], B[t+256], a, b
        //        t <  192     : u[t]
        //        t >=  64     : v[t-64]
        //        t <   64     : A3[t]          (A[512+t])
        //        t >= 192     : B3[t-192]      (B[512+t-192])
        const float4* gA = (const float4*)(x2 + base * 9);   // 576 float4
        const float4* gB = (const float4*)(y2 + base * 9);   // 576 float4
        const float4* gu = (const float4*)(x1 + base * 3);   // 192 float4
        const float4* gv = (const float4*)(y1 + base * 3);   // 192 float4

        const bool mu = (t < 192);
        const bool mv = (t >= 64);
        const bool mA3 = (t < 64);
        const bool mB3 = (t >= 192);

        float4 rA0 = ldcs4(gA + t);
        float4 rB0 = ldcs4(gB + t);
        float4 rA1 = ldcs4(gA + t + 256);
        float4 rB1 = ldcs4(gB + t + 256);
        a = __ldcs(x0 + base + t);
        b = __ldcs(y0 + base + t);
        float4 ru, rv, rex;
        if (mu)  ru  = ldcs4(gu + t);
        if (mv)  rv  = ldcs4(gv + (t - 64));
        if (mA3) rex = ldcs4(gA + t + 512);
        if (mB3) rex = ldcs4(gB + (t - 192) + 512);

        float4* s4A = (float4*)sA;
        float4* s4B = (float4*)sB;
        float4* s4u = (float4*)su;
        float4* s4v = (float4*)sv;
        s4A[t]       = rA0;
        s4B[t]       = rB0;
        s4A[t + 256] = rA1;
        s4B[t + 256] = rB1;
        if (mu)  s4u[t] = ru;
        if (mv)  s4v[t - 64] = rv;
        if (mA3) s4A[t + 512] = rex;
        if (mB3) s4B[(t - 192) + 512] = rex;
    } else {
        for (int i = t; i < npair * 9; i += TPB) { sA[i] = x2[base * 9 + i]; sB[i] = y2[base * 9 + i]; }
        for (int i = t; i < npair * 3; i += TPB) { su[i] = x1[base * 3 + i]; sv[i] = y1[base * 3 + i]; }
        if (t < npair) { a = x0[base + t]; b = y0[base + t]; }
    }
    __syncthreads();

    // ---- Per-pair compute. z1/z2 written straight back into this thread's
    //      OWN smem slots (slot t touched only by thread t between the two
    //      barriers). z0 stored directly to global (coalesced scalar). ----
    if (t < npair) {
        float u[3], v[3], A[9], B[9];
        #pragma unroll
        for (int i = 0; i < 3; i++) { u[i] = su[t * 3 + i]; v[i] = sv[t * 3 + i]; }
        #pragma unroll
        for (int i = 0; i < 9; i++) { A[i] = sA[t * 9 + i]; B[i] = sB[t * 9 + i]; }

        // z2 = a*B + b*A + u (x) v + A@B  -> sA[t*9+..]
        #pragma unroll
        for (int i = 0; i < 3; i++) {
            #pragma unroll
            for (int j = 0; j < 3; j++) {
                float s = fmaf(a, B[i * 3 + j], b * A[i * 3 + j]);
                s = fmaf(u[i], v[j], s);
                #pragma unroll
                for (int k = 0; k < 3; k++)
                    s = fmaf(A[i * 3 + k], B[k * 3 + j], s);
                sA[t * 9 + i * 3 + j] = s;
            }
        }
        // z1 = a*v + b*u + u.B + A.v  -> su[t*3+..]
        #pragma unroll
        for (int i = 0; i < 3; i++) {
            float s = fmaf(a, v[i], b * u[i]);
            #pragma unroll
            for (int d = 0; d < 3; d++) {
                s = fmaf(u[d], B[d * 3 + i], s);
                s = fmaf(A[i * 3 + d], v[d], s);
            }
            su[t * 3 + i] = s;
        }
        // z0 = a*b + u.v + <A,B>  -> direct global store (coalesced)
        float z0 = a * b;
        #pragma unroll
        for (int i = 0; i < 3; i++) z0 = fmaf(u[i], v[i], z0);
        #pragma unroll
        for (int i = 0; i < 9; i++) z0 = fmaf(A[i], B[i], z0);
        __stcs(out + base + t, z0);
    }
    __syncthreads();

    // ---- Coalesced streaming stores, exactly 3 f4 per thread:
    //        every thread : g2[t], g2[t+256]
    //        t <  192     : g1[t]
    //        t >= 192     : g2[512 + (t-192)]
    float* o1 = out + NC;
    float* o2 = out + 4 * NC;
    if (full) {
        float4* g1 = (float4*)(o1 + base * 3);
        float4* g2 = (float4*)(o2 + base * 9);
        const float4* s41 = (const float4*)su;
        const float4* s42 = (const float4*)sA;
        stcs4(g2 + t,       s42[t]);
        stcs4(g2 + t + 256, s42[t + 256]);
        if (t < 192) stcs4(g1 + t, s41[t]);
        else         stcs4(g2 + 512 + (t - 192), s42[512 + (t - 192)]);
    } else {
        for (int i = t; i < npair * 3; i += TPB) o1[base * 3 + i] = su[i];
        for (int i = t; i < npair * 9; i += TPB) o2[base * 9 + i] = sA[i];
    }
}

extern "C" void kernel_launch(void* const* d_in, const int* in_sizes, int n_in,
                              void* d_out, int out_size)
{
    // out = (z0, z1, z2) concatenated: 13*NC floats
    const long long NC = (long long)out_size / 13;

    // Classify inputs by element count; x precedes y within each size class
    // in both plausible metadata orderings.
    const float *x0 = nullptr, *y0 = nullptr, *x1 = nullptr, *y1 = nullptr,
                *x2 = nullptr, *y2 = nullptr;
    for (int i = 0; i < n_in; i++) {
        long long s = in_sizes[i];
        const float* p = (const float*)d_in[i];
        if (s == NC)          { if (!x0) x0 = p; else y0 = p; }
        else if (s == 3 * NC) { if (!x1) x1 = p; else y1 = p; }
        else if (s == 9 * NC) { if (!x2) x2 = p; else y2 = p; }
    }

    const int nblocks = (int)((NC + TPB - 1) / TPB);
    tp_kernel<<<nblocks, TPB>>>(x0, y0, x1, y1, x2, y2, (float*)d_out, NC);
}